// round 2
// baseline (speedup 1.0000x reference)
#include <cuda_runtime.h>
#include <math.h>

// ---------------- Problem constants ----------------
#define B_ 4
#define N_ 1025
#define C_ 768
#define H_ 12
#define D_ 64
#define TOPT 103
#define SCALEF 0.125f            // 64^-0.5

static const int M_TOT = B_ * N_;      // 4100

// Output layout (float32, reference tuple flattened & concatenated):
//   out            [4,1025,768]  = 3148800
//   enhance_index  [4,103,768]   =  316416
//   enh_idx        [4,103]       =     412
//   fuse_index     [4,103,768]   =  316416
//   fuse_idx       [4,103]       =     412
//   cls_attn       [4,1024]      =    4096
#define OFF_OUT        0L
#define OFF_ENH_INDEX  3148800L
#define OFF_ENH_IDX    3465216L
#define OFF_FUSE_INDEX 3465628L
#define OFF_FUSE_IDX   3782044L
#define OFF_CLS        3782456L

// ---------------- Scratch (no allocation allowed) ----------------
__device__ float  g_q[B_*H_*N_*D_];     // [b,h,n,d]
__device__ float  g_k[B_*H_*N_*D_];
__device__ float  g_v[B_*H_*N_*D_];
__device__ float  g_ctx[B_*N_*C_];      // [b,n,h*64+d]
__device__ double g_clsd[B_*(N_-1)];    // high-precision cls_attn for ranking

// ======================================================================
// Kernel 1: QKV projection. qkv[m, j] = sum_k x[m,k] * w_qkv[j,k]
// Tile 64x64, BK=16, 256 threads, 4x4 per thread. Scatter to g_q/g_k/g_v.
// ======================================================================
__global__ void qkv_gemm(const float* __restrict__ A, const float* __restrict__ W) {
    __shared__ float As[16][68];
    __shared__ float Bs[16][68];
    const int tid = threadIdx.x;
    const int ty = tid >> 4, tx = tid & 15;
    const int m0 = blockIdx.y * 64;
    const int n0 = blockIdx.x * 64;

    float acc[4][4] = {};
    for (int kt = 0; kt < C_; kt += 16) {
        #pragma unroll
        for (int t = 0; t < 4; t++) {
            int idx = tid + t * 256;
            int m = idx >> 4, k = idx & 15;
            int gm = m0 + m;
            As[k][m] = (gm < M_TOT) ? A[(long)gm * C_ + kt + k] : 0.f;
            int gn = n0 + m;
            Bs[k][m] = W[(long)gn * C_ + kt + k];
        }
        __syncthreads();
        #pragma unroll
        for (int kk = 0; kk < 16; kk++) {
            float a[4], b2[4];
            #pragma unroll
            for (int i = 0; i < 4; i++) a[i]  = As[kk][ty*4 + i];
            #pragma unroll
            for (int j = 0; j < 4; j++) b2[j] = Bs[kk][tx*4 + j];
            #pragma unroll
            for (int i = 0; i < 4; i++)
                #pragma unroll
                for (int j = 0; j < 4; j++)
                    acc[i][j] = fmaf(a[i], b2[j], acc[i][j]);
        }
        __syncthreads();
    }
    // scatter (tile is 64 wide => single (qkv,h) block since n0 % 64 == 0)
    int qkv_i = n0 / C_;
    int h = (n0 % C_) >> 6;
    float* dst = (qkv_i == 0) ? g_q : (qkv_i == 1 ? g_k : g_v);
    #pragma unroll
    for (int i = 0; i < 4; i++) {
        int gm = m0 + ty*4 + i;
        if (gm < M_TOT) {
            int b = gm / N_, n = gm % N_;
            long base = ((long)(b * H_ + h) * N_ + n) * 64;
            #pragma unroll
            for (int j = 0; j < 4; j++)
                dst[base + tx*4 + j] = acc[i][j];
        }
    }
}

// ======================================================================
// Kernel 2: flash attention with CSA mask. One CTA = (bh, 64-query tile).
// ======================================================================
__global__ void attn_kernel() {
    extern __shared__ float sm[];
    float* Qs = sm;                // 64 x 65
    float* Ks = sm + 64*65;
    float* Vs = sm + 2*64*65;
    float* Ps = sm + 3*64*65;

    const int tid = threadIdx.x;
    const int ty = tid >> 4, tx = tid & 15;
    const int bh = blockIdx.y;
    const int q0g = blockIdx.x * 64;
    const float* Qg = g_q + (long)bh * N_ * 64;
    const float* Kg = g_k + (long)bh * N_ * 64;
    const float* Vg = g_v + (long)bh * N_ * 64;

    for (int idx = tid; idx < 64*64; idx += 256) {
        int r = idx >> 6, d = idx & 63;
        int qi = q0g + r;
        Qs[r*65 + d] = (qi < N_) ? Qg[(long)qi*64 + d] : 0.f;
    }

    float acc[4][4] = {};
    float m_i[4], l_i[4];
    #pragma unroll
    for (int i = 0; i < 4; i++) { m_i[i] = -INFINITY; l_i[i] = 0.f; }

    const int r0 = ty*4, c0 = tx*4;

    for (int kt = 0; kt < 17; kt++) {
        const int k0g = kt * 64;
        __syncthreads();
        for (int idx = tid; idx < 64*64; idx += 256) {
            int r = idx >> 6, d = idx & 63;
            int kj = k0g + r;
            Ks[r*65 + d] = (kj < N_) ? Kg[(long)kj*64 + d] : 0.f;
            Vs[r*65 + d] = (kj < N_) ? Vg[(long)kj*64 + d] : 0.f;
        }
        __syncthreads();

        float sv[4][4] = {};
        #pragma unroll 8
        for (int kk = 0; kk < 64; kk++) {
            float a[4], b2[4];
            #pragma unroll
            for (int i = 0; i < 4; i++) a[i]  = Qs[(r0+i)*65 + kk];
            #pragma unroll
            for (int j = 0; j < 4; j++) b2[j] = Ks[(c0+j)*65 + kk];
            #pragma unroll
            for (int i = 0; i < 4; i++)
                #pragma unroll
                for (int j = 0; j < 4; j++)
                    sv[i][j] = fmaf(a[i], b2[j], sv[i][j]);
        }

        // scale + CSA mask
        #pragma unroll
        for (int i = 0; i < 4; i++) {
            int qi = q0g + r0 + i;
            int qb = (qi >= 1) ? ((qi - 1) >> 8) : -1;
            #pragma unroll
            for (int j = 0; j < 4; j++) {
                int kj = k0g + c0 + j;
                float s = sv[i][j] * SCALEF;
                bool bad = (kj >= N_) ||
                           (qb >= 0 && kj >= 1 && (((kj - 1) >> 8) == qb));
                sv[i][j] = bad ? -INFINITY : s;
            }
        }

        // online softmax update
        #pragma unroll
        for (int i = 0; i < 4; i++) {
            float t = fmaxf(fmaxf(sv[i][0], sv[i][1]), fmaxf(sv[i][2], sv[i][3]));
            #pragma unroll
            for (int o = 8; o >= 1; o >>= 1)
                t = fmaxf(t, __shfl_xor_sync(0xffffffffu, t, o));
            float mnew = fmaxf(m_i[i], t);
            float corr = __expf(m_i[i] - mnew);
            m_i[i] = mnew;

            float p[4], rs = 0.f;
            #pragma unroll
            for (int j = 0; j < 4; j++) {
                p[j] = __expf(sv[i][j] - mnew);
                rs += p[j];
                Ps[(r0+i)*65 + c0 + j] = p[j];
            }
            #pragma unroll
            for (int o = 8; o >= 1; o >>= 1)
                rs += __shfl_xor_sync(0xffffffffu, rs, o);
            l_i[i] = l_i[i] * corr + rs;
            #pragma unroll
            for (int j = 0; j < 4; j++) acc[i][j] *= corr;
        }
        __syncthreads();

        // O += P @ V   (d-columns = c0..c0+3)
        #pragma unroll 8
        for (int jj = 0; jj < 64; jj++) {
            float p[4], v2[4];
            #pragma unroll
            for (int i = 0; i < 4; i++) p[i]  = Ps[(r0+i)*65 + jj];
            #pragma unroll
            for (int j = 0; j < 4; j++) v2[j] = Vs[jj*65 + c0 + j];
            #pragma unroll
            for (int i = 0; i < 4; i++)
                #pragma unroll
                for (int j = 0; j < 4; j++)
                    acc[i][j] = fmaf(p[i], v2[j], acc[i][j]);
        }
    }

    const int b = bh / H_, h = bh % H_;
    #pragma unroll
    for (int i = 0; i < 4; i++) {
        int qi = q0g + r0 + i;
        if (qi < N_) {
            float inv = 1.f / l_i[i];
            long base = ((long)b * N_ + qi) * C_ + h * 64 + c0;
            #pragma unroll
            for (int j = 0; j < 4; j++)
                g_ctx[base + j] = acc[i][j] * inv;
        }
    }
}

// ======================================================================
// Kernel 3: output projection.  out[m,c] = ctx[m,:] . w_out[c,:] + b_out[c]
// ======================================================================
__global__ void out_gemm(const float* __restrict__ W, const float* __restrict__ bias,
                         float* __restrict__ out) {
    __shared__ float As[16][68];
    __shared__ float Bs[16][68];
    const int tid = threadIdx.x;
    const int ty = tid >> 4, tx = tid & 15;
    const int m0 = blockIdx.y * 64;
    const int n0 = blockIdx.x * 64;

    float acc[4][4] = {};
    for (int kt = 0; kt < C_; kt += 16) {
        #pragma unroll
        for (int t = 0; t < 4; t++) {
            int idx = tid + t * 256;
            int m = idx >> 4, k = idx & 15;
            int gm = m0 + m;
            As[k][m] = (gm < M_TOT) ? g_ctx[(long)gm * C_ + kt + k] : 0.f;
            int gn = n0 + m;
            Bs[k][m] = W[(long)gn * C_ + kt + k];
        }
        __syncthreads();
        #pragma unroll
        for (int kk = 0; kk < 16; kk++) {
            float a[4], b2[4];
            #pragma unroll
            for (int i = 0; i < 4; i++) a[i]  = As[kk][ty*4 + i];
            #pragma unroll
            for (int j = 0; j < 4; j++) b2[j] = Bs[kk][tx*4 + j];
            #pragma unroll
            for (int i = 0; i < 4; i++)
                #pragma unroll
                for (int j = 0; j < 4; j++)
                    acc[i][j] = fmaf(a[i], b2[j], acc[i][j]);
        }
        __syncthreads();
    }
    #pragma unroll
    for (int i = 0; i < 4; i++) {
        int gm = m0 + ty*4 + i;
        if (gm < M_TOT) {
            #pragma unroll
            for (int j = 0; j < 4; j++) {
                int c = n0 + tx*4 + j;
                out[OFF_OUT + (long)gm * C_ + c] = acc[i][j] + bias[c];
            }
        }
    }
}

// ======================================================================
// Kernel 4: cls attention row -- DOUBLE PRECISION path.
// s_j = (q0 . k_j) in fp64, exact exp(), fp64 reductions and head-mean.
// One CTA per batch, serial over heads (deterministic).
// ======================================================================
__global__ void cls_kernel(float* __restrict__ out) {
    __shared__ float  q0s[64];
    __shared__ double s[N_];
    __shared__ double accm[N_ - 1];
    __shared__ double red[256];
    const int b = blockIdx.x, tid = threadIdx.x;

    for (int j = tid; j < N_ - 1; j += 256) accm[j] = 0.0;

    for (int h = 0; h < H_; h++) {
        __syncthreads();
        if (tid < 64) q0s[tid] = g_q[(long)(b * H_ + h) * N_ * 64 + tid];
        __syncthreads();
        const float* Kg = g_k + (long)(b * H_ + h) * N_ * 64;
        for (int j = tid; j < N_; j += 256) {
            double a = 0.0;
            #pragma unroll 8
            for (int d = 0; d < 64; d++)
                a += (double)q0s[d] * (double)Kg[(long)j*64 + d];
            s[j] = a * 0.125;       // row 0 is unmasked everywhere
        }
        __syncthreads();
        // block max (fp64)
        double lm = -1e300;
        for (int j = tid; j < N_; j += 256) lm = fmax(lm, s[j]);
        red[tid] = lm; __syncthreads();
        for (int o = 128; o >= 1; o >>= 1) {
            if (tid < o) red[tid] = fmax(red[tid], red[tid + o]);
            __syncthreads();
        }
        double m = red[0];
        __syncthreads();
        // block sum of exp (fp64)
        double ls = 0.0;
        for (int j = tid; j < N_; j += 256) ls += exp(s[j] - m);
        red[tid] = ls; __syncthreads();
        for (int o = 128; o >= 1; o >>= 1) {
            if (tid < o) red[tid] += red[tid + o];
            __syncthreads();
        }
        double inv = 1.0 / red[0];
        __syncthreads();
        for (int j = tid; j < N_ - 1; j += 256)
            accm[j] += exp(s[j + 1] - m) * inv * (1.0 / 12.0);
    }
    __syncthreads();
    for (int j = tid; j < N_ - 1; j += 256) {
        double v = accm[j];
        g_clsd[b * (N_ - 1) + j] = v;
        out[OFF_CLS + (long)b * (N_ - 1) + j] = (float)v;
    }
}

// ======================================================================
// Kernel 5: dual bitonic top-k (103 of 1024) on fp64 keys, jax top_k
// tie-break (lower index wins). Pass 0: descending (enh). Pass 1: ascending.
// ======================================================================
__global__ void sort_kernel(float* __restrict__ out) {
    __shared__ double v[1024];
    __shared__ int ix[1024];
    const int b = blockIdx.x, tid = threadIdx.x;

    for (int pass = 0; pass < 2; pass++) {
        __syncthreads();
        for (int i = tid; i < 1024; i += 512) {
            v[i] = g_clsd[b * 1024 + i];
            ix[i] = i;
        }
        __syncthreads();
        const bool desc = (pass == 0);
        for (int k = 2; k <= 1024; k <<= 1) {
            for (int j = k >> 1; j > 0; j >>= 1) {
                for (int i = tid; i < 1024; i += 512) {
                    int p = i ^ j;
                    if (p > i) {
                        double va = v[i], vb = v[p];
                        int ia = ix[i], ib = ix[p];
                        bool ab = desc ? (va > vb || (va == vb && ia < ib))
                                       : (va < vb || (va == vb && ia < ib));
                        bool up = ((i & k) == 0);
                        if (up ? !ab : ab) {
                            v[i] = vb; v[p] = va;
                            ix[i] = ib; ix[p] = ia;
                        }
                    }
                }
                __syncthreads();
            }
        }
        const long offIdx = desc ? OFF_ENH_IDX : OFF_FUSE_IDX;
        const long offBrd = desc ? OFF_ENH_INDEX : OFF_FUSE_INDEX;
        for (int t = tid; t < TOPT; t += 512)
            out[offIdx + (long)b * TOPT + t] = (float)ix[t];
        for (int e = tid; e < TOPT * C_; e += 512) {
            int t = e / C_;
            out[offBrd + ((long)b * TOPT + t) * C_ + (e % C_)] = (float)ix[t];
        }
    }
}

// ======================================================================
// Launch
// ======================================================================
extern "C" void kernel_launch(void* const* d_in, const int* in_sizes, int n_in,
                              void* d_out, int out_size) {
    const float* x     = (const float*)d_in[0];
    const float* w_qkv = (const float*)d_in[1];
    const float* w_out = (const float*)d_in[2];
    const float* b_out = (const float*)d_in[3];
    float* out = (float*)d_out;

    const int ATTN_SMEM = 4 * 64 * 65 * (int)sizeof(float);   // 66560 B
    cudaFuncSetAttribute(attn_kernel, cudaFuncAttributeMaxDynamicSharedMemorySize,
                         ATTN_SMEM);

    qkv_gemm<<<dim3(3 * C_ / 64, (M_TOT + 63) / 64), 256>>>(x, w_qkv);
    attn_kernel<<<dim3(17, B_ * H_), 256, ATTN_SMEM>>>();
    out_gemm<<<dim3(C_ / 64, (M_TOT + 63) / 64), 256>>>(w_out, b_out, out);
    cls_kernel<<<B_, 256>>>(out);
    sort_kernel<<<B_, 512>>>(out);
}

// round 3
// speedup vs baseline: 1.6111x; 1.6111x over previous
#include <cuda_runtime.h>
#include <math.h>

// ---------------- Problem constants ----------------
#define B_ 4
#define N_ 1025
#define C_ 768
#define H_ 12
#define D_ 64
#define TOPT 103
#define SCALEF 0.125f            // 64^-0.5

static const int M_TOT = B_ * N_;      // 4100

// Output layout (float32, reference tuple flattened & concatenated):
#define OFF_OUT        0L
#define OFF_ENH_INDEX  3148800L
#define OFF_ENH_IDX    3465216L
#define OFF_FUSE_INDEX 3465628L
#define OFF_FUSE_IDX   3782044L
#define OFF_CLS        3782456L

// ---------------- Scratch (no allocation allowed) ----------------
__device__ float  g_q[B_*H_*N_*D_];     // [b,h,n,d]
__device__ float  g_k[B_*H_*N_*D_];
__device__ float  g_v[B_*H_*N_*D_];
__device__ float  g_ctx[B_*N_*C_];      // [b,n,h*64+d]
__device__ double g_clsd[B_*(N_-1)];    // high-precision cls_attn for ranking
__device__ double g_cls_ph[B_*H_][N_-1];// per-head softmax row (prob of keys 1..1024)

// ======================================================================
// Kernel 1: QKV projection. qkv[m, j] = sum_k x[m,k] * w_qkv[j,k]
// Tile 64x64, BK=16, 256 threads, 4x4 per thread. Scatter to g_q/g_k/g_v.
// ======================================================================
__global__ void qkv_gemm(const float* __restrict__ A, const float* __restrict__ W) {
    __shared__ float As[16][68];
    __shared__ float Bs[16][68];
    const int tid = threadIdx.x;
    const int ty = tid >> 4, tx = tid & 15;
    const int m0 = blockIdx.y * 64;
    const int n0 = blockIdx.x * 64;

    float acc[4][4] = {};
    for (int kt = 0; kt < C_; kt += 16) {
        #pragma unroll
        for (int t = 0; t < 4; t++) {
            int idx = tid + t * 256;
            int m = idx >> 4, k = idx & 15;
            int gm = m0 + m;
            As[k][m] = (gm < M_TOT) ? A[(long)gm * C_ + kt + k] : 0.f;
            int gn = n0 + m;
            Bs[k][m] = W[(long)gn * C_ + kt + k];
        }
        __syncthreads();
        #pragma unroll
        for (int kk = 0; kk < 16; kk++) {
            float a[4], b2[4];
            #pragma unroll
            for (int i = 0; i < 4; i++) a[i]  = As[kk][ty*4 + i];
            #pragma unroll
            for (int j = 0; j < 4; j++) b2[j] = Bs[kk][tx*4 + j];
            #pragma unroll
            for (int i = 0; i < 4; i++)
                #pragma unroll
                for (int j = 0; j < 4; j++)
                    acc[i][j] = fmaf(a[i], b2[j], acc[i][j]);
        }
        __syncthreads();
    }
    int qkv_i = n0 / C_;
    int h = (n0 % C_) >> 6;
    float* dst = (qkv_i == 0) ? g_q : (qkv_i == 1 ? g_k : g_v);
    #pragma unroll
    for (int i = 0; i < 4; i++) {
        int gm = m0 + ty*4 + i;
        if (gm < M_TOT) {
            int b = gm / N_, n = gm % N_;
            long base = ((long)(b * H_ + h) * N_ + n) * 64;
            #pragma unroll
            for (int j = 0; j < 4; j++)
                dst[base + tx*4 + j] = acc[i][j];
        }
    }
}

// ======================================================================
// Kernel 2: flash attention with CSA mask. One CTA = (bh, 64-query tile).
// ======================================================================
__global__ void attn_kernel() {
    extern __shared__ float sm[];
    float* Qs = sm;                // 64 x 65
    float* Ks = sm + 64*65;
    float* Vs = sm + 2*64*65;
    float* Ps = sm + 3*64*65;

    const int tid = threadIdx.x;
    const int ty = tid >> 4, tx = tid & 15;
    const int bh = blockIdx.y;
    const int q0g = blockIdx.x * 64;
    const float* Qg = g_q + (long)bh * N_ * 64;
    const float* Kg = g_k + (long)bh * N_ * 64;
    const float* Vg = g_v + (long)bh * N_ * 64;

    for (int idx = tid; idx < 64*64; idx += 256) {
        int r = idx >> 6, d = idx & 63;
        int qi = q0g + r;
        Qs[r*65 + d] = (qi < N_) ? Qg[(long)qi*64 + d] : 0.f;
    }

    float acc[4][4] = {};
    float m_i[4], l_i[4];
    #pragma unroll
    for (int i = 0; i < 4; i++) { m_i[i] = -INFINITY; l_i[i] = 0.f; }

    const int r0 = ty*4, c0 = tx*4;

    for (int kt = 0; kt < 17; kt++) {
        const int k0g = kt * 64;
        __syncthreads();
        for (int idx = tid; idx < 64*64; idx += 256) {
            int r = idx >> 6, d = idx & 63;
            int kj = k0g + r;
            Ks[r*65 + d] = (kj < N_) ? Kg[(long)kj*64 + d] : 0.f;
            Vs[r*65 + d] = (kj < N_) ? Vg[(long)kj*64 + d] : 0.f;
        }
        __syncthreads();

        float sv[4][4] = {};
        #pragma unroll 8
        for (int kk = 0; kk < 64; kk++) {
            float a[4], b2[4];
            #pragma unroll
            for (int i = 0; i < 4; i++) a[i]  = Qs[(r0+i)*65 + kk];
            #pragma unroll
            for (int j = 0; j < 4; j++) b2[j] = Ks[(c0+j)*65 + kk];
            #pragma unroll
            for (int i = 0; i < 4; i++)
                #pragma unroll
                for (int j = 0; j < 4; j++)
                    sv[i][j] = fmaf(a[i], b2[j], sv[i][j]);
        }

        #pragma unroll
        for (int i = 0; i < 4; i++) {
            int qi = q0g + r0 + i;
            int qb = (qi >= 1) ? ((qi - 1) >> 8) : -1;
            #pragma unroll
            for (int j = 0; j < 4; j++) {
                int kj = k0g + c0 + j;
                float s = sv[i][j] * SCALEF;
                bool bad = (kj >= N_) ||
                           (qb >= 0 && kj >= 1 && (((kj - 1) >> 8) == qb));
                sv[i][j] = bad ? -INFINITY : s;
            }
        }

        #pragma unroll
        for (int i = 0; i < 4; i++) {
            float t = fmaxf(fmaxf(sv[i][0], sv[i][1]), fmaxf(sv[i][2], sv[i][3]));
            #pragma unroll
            for (int o = 8; o >= 1; o >>= 1)
                t = fmaxf(t, __shfl_xor_sync(0xffffffffu, t, o));
            float mnew = fmaxf(m_i[i], t);
            float corr = __expf(m_i[i] - mnew);
            m_i[i] = mnew;

            float p[4], rs = 0.f;
            #pragma unroll
            for (int j = 0; j < 4; j++) {
                p[j] = __expf(sv[i][j] - mnew);
                rs += p[j];
                Ps[(r0+i)*65 + c0 + j] = p[j];
            }
            #pragma unroll
            for (int o = 8; o >= 1; o >>= 1)
                rs += __shfl_xor_sync(0xffffffffu, rs, o);
            l_i[i] = l_i[i] * corr + rs;
            #pragma unroll
            for (int j = 0; j < 4; j++) acc[i][j] *= corr;
        }
        __syncthreads();

        #pragma unroll 8
        for (int jj = 0; jj < 64; jj++) {
            float p[4], v2[4];
            #pragma unroll
            for (int i = 0; i < 4; i++) p[i]  = Ps[(r0+i)*65 + jj];
            #pragma unroll
            for (int j = 0; j < 4; j++) v2[j] = Vs[jj*65 + c0 + j];
            #pragma unroll
            for (int i = 0; i < 4; i++)
                #pragma unroll
                for (int j = 0; j < 4; j++)
                    acc[i][j] = fmaf(p[i], v2[j], acc[i][j]);
        }
    }

    const int b = bh / H_, h = bh % H_;
    #pragma unroll
    for (int i = 0; i < 4; i++) {
        int qi = q0g + r0 + i;
        if (qi < N_) {
            float inv = 1.f / l_i[i];
            long base = ((long)b * N_ + qi) * C_ + h * 64 + c0;
            #pragma unroll
            for (int j = 0; j < 4; j++)
                g_ctx[base + j] = acc[i][j] * inv;
        }
    }
}

// ======================================================================
// Kernel 3: output projection.  out[m,c] = ctx[m,:] . w_out[c,:] + b_out[c]
// ======================================================================
__global__ void out_gemm(const float* __restrict__ W, const float* __restrict__ bias,
                         float* __restrict__ out) {
    __shared__ float As[16][68];
    __shared__ float Bs[16][68];
    const int tid = threadIdx.x;
    const int ty = tid >> 4, tx = tid & 15;
    const int m0 = blockIdx.y * 64;
    const int n0 = blockIdx.x * 64;

    float acc[4][4] = {};
    for (int kt = 0; kt < C_; kt += 16) {
        #pragma unroll
        for (int t = 0; t < 4; t++) {
            int idx = tid + t * 256;
            int m = idx >> 4, k = idx & 15;
            int gm = m0 + m;
            As[k][m] = (gm < M_TOT) ? g_ctx[(long)gm * C_ + kt + k] : 0.f;
            int gn = n0 + m;
            Bs[k][m] = W[(long)gn * C_ + kt + k];
        }
        __syncthreads();
        #pragma unroll
        for (int kk = 0; kk < 16; kk++) {
            float a[4], b2[4];
            #pragma unroll
            for (int i = 0; i < 4; i++) a[i]  = As[kk][ty*4 + i];
            #pragma unroll
            for (int j = 0; j < 4; j++) b2[j] = Bs[kk][tx*4 + j];
            #pragma unroll
            for (int i = 0; i < 4; i++)
                #pragma unroll
                for (int j = 0; j < 4; j++)
                    acc[i][j] = fmaf(a[i], b2[j], acc[i][j]);
        }
        __syncthreads();
    }
    #pragma unroll
    for (int i = 0; i < 4; i++) {
        int gm = m0 + ty*4 + i;
        if (gm < M_TOT) {
            #pragma unroll
            for (int j = 0; j < 4; j++) {
                int c = n0 + tx*4 + j;
                out[OFF_OUT + (long)gm * C_ + c] = acc[i][j] + bias[c];
            }
        }
    }
}

// ======================================================================
// Kernel 4a: per-head cls softmax row (fp64). One CTA per (b,h) = 48 CTAs.
// Warp-per-key-row dot product: lane d sums d and d+32 -> shfl reduce.
// ======================================================================
__global__ void cls_head_kernel() {
    __shared__ double q0s[64];
    __shared__ double s[N_];
    __shared__ double red[8];
    const int bh = blockIdx.x;
    const int tid = threadIdx.x;
    const int wid = tid >> 5, lane = tid & 31;

    const float* Qg = g_q + (long)bh * N_ * 64;
    const float* Kg = g_k + (long)bh * N_ * 64;

    if (tid < 64) q0s[tid] = (double)Qg[tid];
    __syncthreads();

    // warp-per-j dot product
    const double qa = q0s[lane], qb = q0s[lane + 32];
    for (int j = wid; j < N_; j += 8) {
        const float* kr = Kg + (long)j * 64;
        double a = qa * (double)kr[lane] + qb * (double)kr[lane + 32];
        #pragma unroll
        for (int o = 16; o >= 1; o >>= 1)
            a += __shfl_xor_sync(0xffffffffu, a, o);
        if (lane == 0) s[j] = a * 0.125;
    }
    __syncthreads();

    // block max (fp64)
    double lm = -1e300;
    for (int j = tid; j < N_; j += 256) lm = fmax(lm, s[j]);
    #pragma unroll
    for (int o = 16; o >= 1; o >>= 1)
        lm = fmax(lm, __shfl_xor_sync(0xffffffffu, lm, o));
    if (lane == 0) red[wid] = lm;
    __syncthreads();
    double m = red[0];
    #pragma unroll
    for (int w = 1; w < 8; w++) m = fmax(m, red[w]);
    __syncthreads();

    // block sum of exp (fp64): deterministic two-stage (strided partials fixed order)
    double ls = 0.0;
    for (int j = tid; j < N_; j += 256) ls += exp(s[j] - m);
    #pragma unroll
    for (int o = 16; o >= 1; o >>= 1)
        ls += __shfl_xor_sync(0xffffffffu, ls, o);
    if (lane == 0) red[wid] = ls;
    __syncthreads();
    double tot = 0.0;
    #pragma unroll
    for (int w = 0; w < 8; w++) tot += red[w];
    double inv = 1.0 / tot;

    for (int j = tid; j < N_ - 1; j += 256)
        g_cls_ph[bh][j] = exp(s[j + 1] - m) * inv;
}

// ======================================================================
// Kernel 4b: head-mean reduce (fp64, h-ascending order). One CTA per batch.
// ======================================================================
__global__ void cls_reduce_kernel(float* __restrict__ out) {
    const int b = blockIdx.x, tid = threadIdx.x;
    for (int j = tid; j < N_ - 1; j += 256) {
        double a = 0.0;
        #pragma unroll
        for (int h = 0; h < H_; h++)
            a += g_cls_ph[b * H_ + h][j] * (1.0 / 12.0);
        g_clsd[b * (N_ - 1) + j] = a;
        out[OFF_CLS + (long)b * (N_ - 1) + j] = (float)a;
    }
}

// ======================================================================
// Kernel 5: dual bitonic top-k (103 of 1024) on fp64 keys, jax top_k
// tie-break (lower index wins). Pass 0: descending (enh). Pass 1: ascending.
// ======================================================================
__global__ void sort_kernel(float* __restrict__ out) {
    __shared__ double v[1024];
    __shared__ int ix[1024];
    const int b = blockIdx.x, tid = threadIdx.x;

    for (int pass = 0; pass < 2; pass++) {
        __syncthreads();
        for (int i = tid; i < 1024; i += 512) {
            v[i] = g_clsd[b * 1024 + i];
            ix[i] = i;
        }
        __syncthreads();
        const bool desc = (pass == 0);
        for (int k = 2; k <= 1024; k <<= 1) {
            for (int j = k >> 1; j > 0; j >>= 1) {
                for (int i = tid; i < 1024; i += 512) {
                    int p = i ^ j;
                    if (p > i) {
                        double va = v[i], vb = v[p];
                        int ia = ix[i], ib = ix[p];
                        bool ab = desc ? (va > vb || (va == vb && ia < ib))
                                       : (va < vb || (va == vb && ia < ib));
                        bool up = ((i & k) == 0);
                        if (up ? !ab : ab) {
                            v[i] = vb; v[p] = va;
                            ix[i] = ib; ix[p] = ia;
                        }
                    }
                }
                __syncthreads();
            }
        }
        const long offIdx = desc ? OFF_ENH_IDX : OFF_FUSE_IDX;
        const long offBrd = desc ? OFF_ENH_INDEX : OFF_FUSE_INDEX;
        for (int t = tid; t < TOPT; t += 512)
            out[offIdx + (long)b * TOPT + t] = (float)ix[t];
        for (int e = tid; e < TOPT * C_; e += 512) {
            int t = e / C_;
            out[offBrd + ((long)b * TOPT + t) * C_ + (e % C_)] = (float)ix[t];
        }
    }
}

// ======================================================================
// Launch
// ======================================================================
extern "C" void kernel_launch(void* const* d_in, const int* in_sizes, int n_in,
                              void* d_out, int out_size) {
    const float* x     = (const float*)d_in[0];
    const float* w_qkv = (const float*)d_in[1];
    const float* w_out = (const float*)d_in[2];
    const float* b_out = (const float*)d_in[3];
    float* out = (float*)d_out;

    const int ATTN_SMEM = 4 * 64 * 65 * (int)sizeof(float);   // 66560 B
    cudaFuncSetAttribute(attn_kernel, cudaFuncAttributeMaxDynamicSharedMemorySize,
                         ATTN_SMEM);

    qkv_gemm<<<dim3(3 * C_ / 64, (M_TOT + 63) / 64), 256>>>(x, w_qkv);
    attn_kernel<<<dim3(17, B_ * H_), 256, ATTN_SMEM>>>();
    out_gemm<<<dim3(C_ / 64, (M_TOT + 63) / 64), 256>>>(w_out, b_out, out);
    cls_head_kernel<<<B_ * H_, 256>>>();
    cls_reduce_kernel<<<B_, 256>>>(out);
    sort_kernel<<<B_, 512>>>(out);
}

// round 4
// speedup vs baseline: 1.7756x; 1.1021x over previous
#include <cuda_runtime.h>
#include <math.h>

// ---------------- Problem constants ----------------
#define B_ 4
#define N_ 1025
#define C_ 768
#define H_ 12
#define D_ 64
#define TOPT 103
#define SCALEF 0.125f            // 64^-0.5

static const int M_TOT = B_ * N_;      // 4100

// Output layout (float32, reference tuple flattened & concatenated):
#define OFF_OUT        0L
#define OFF_ENH_INDEX  3148800L
#define OFF_ENH_IDX    3465216L
#define OFF_FUSE_INDEX 3465628L
#define OFF_FUSE_IDX   3782044L
#define OFF_CLS        3782456L

// ---------------- Scratch (no allocation allowed) ----------------
__device__ float  g_q[B_*H_*N_*D_];     // [b,h,n,d]
__device__ float  g_k[B_*H_*N_*D_];
__device__ float  g_v[B_*H_*N_*D_];
__device__ float  g_ctx[B_*N_*C_];      // [b,n,h*64+d]
__device__ double g_clsd[B_*(N_-1)];    // high-precision cls_attn for ranking
__device__ double g_cls_ph[B_*H_][N_-1];// per-head softmax row (keys 1..1024)

// ======================================================================
// Kernel 1: QKV projection. qkv[m,j] = sum_k x[m,k] * w_qkv[j,k]
// Tile 128x128, BK=16, 256 threads, 8x8 per thread. Scatter to g_q/g_k/g_v.
// ======================================================================
__global__ void __launch_bounds__(256, 2)
qkv_gemm(const float* __restrict__ A, const float* __restrict__ W) {
    __shared__ float As[16][136];
    __shared__ float Bs[16][136];
    const int tid = threadIdx.x;
    const int ty = tid >> 4, tx = tid & 15;
    const int m0 = blockIdx.y * 128;
    const int n0 = blockIdx.x * 128;

    float acc[8][8] = {};
    for (int kt = 0; kt < C_; kt += 16) {
        #pragma unroll
        for (int t = 0; t < 8; t++) {
            int idx = tid + t * 256;
            int m = idx >> 4, k = idx & 15;
            int gm = m0 + m;
            As[k][m] = (gm < M_TOT) ? A[(long)gm * C_ + kt + k] : 0.f;
            int gn = n0 + m;
            Bs[k][m] = W[(long)gn * C_ + kt + k];
        }
        __syncthreads();
        #pragma unroll
        for (int kk = 0; kk < 16; kk++) {
            float a[8], b2[8];
            *(float4*)&a[0]  = *(const float4*)&As[kk][ty*8];
            *(float4*)&a[4]  = *(const float4*)&As[kk][ty*8 + 4];
            *(float4*)&b2[0] = *(const float4*)&Bs[kk][tx*8];
            *(float4*)&b2[4] = *(const float4*)&Bs[kk][tx*8 + 4];
            #pragma unroll
            for (int i = 0; i < 8; i++)
                #pragma unroll
                for (int j = 0; j < 8; j++)
                    acc[i][j] = fmaf(a[i], b2[j], acc[i][j]);
        }
        __syncthreads();
    }
    // scatter: tile 128 wide, 768%128==0 => single qkv matrix; head uniform/thread
    const int qkv_i = n0 / C_;
    const int colm = (n0 % C_) + tx * 8;   // < 768
    const int h = colm >> 6;
    const int d0 = colm & 63;
    float* dst = (qkv_i == 0) ? g_q : (qkv_i == 1 ? g_k : g_v);
    #pragma unroll
    for (int i = 0; i < 8; i++) {
        int gm = m0 + ty*8 + i;
        if (gm < M_TOT) {
            int b = gm / N_, n = gm % N_;
            long base = ((long)(b * H_ + h) * N_ + n) * 64 + d0;
            *(float4*)&dst[base]     = make_float4(acc[i][0], acc[i][1], acc[i][2], acc[i][3]);
            *(float4*)&dst[base + 4] = make_float4(acc[i][4], acc[i][5], acc[i][6], acc[i][7]);
        }
    }
}

// ======================================================================
// Kernel 2: flash attention with CSA mask + fully-masked-tile skipping.
// One CTA = (bh, 64-query tile).
// ======================================================================
__global__ void attn_kernel() {
    extern __shared__ float sm[];
    float* Qs = sm;                // 64 x 65
    float* Ks = sm + 64*65;
    float* Vs = sm + 2*64*65;
    float* Ps = sm + 3*64*65;

    const int tid = threadIdx.x;
    const int ty = tid >> 4, tx = tid & 15;
    const int bh = blockIdx.y;
    const int q0g = blockIdx.x * 64;
    const float* Qg = g_q + (long)bh * N_ * 64;
    const float* Kg = g_k + (long)bh * N_ * 64;
    const float* Vg = g_v + (long)bh * N_ * 64;

    for (int idx = tid; idx < 64*64; idx += 256) {
        int r = idx >> 6, d = idx & 63;
        int qi = q0g + r;
        Qs[r*65 + d] = (qi < N_) ? Qg[(long)qi*64 + d] : 0.f;
    }

    // q-tile CSA block uniformity (for tile skipping). q0g>=64 => all q>=1.
    bool q_uni = false; int qblk = -2;
    if (q0g >= 64) {
        int qhi = min(q0g + 63, N_ - 1);
        int blo = (q0g - 1) >> 8, bhi = (qhi - 1) >> 8;
        if (blo == bhi) { q_uni = true; qblk = blo; }
    }

    float acc[4][4] = {};
    float m_i[4], l_i[4];
    #pragma unroll
    for (int i = 0; i < 4; i++) { m_i[i] = -INFINITY; l_i[i] = 0.f; }

    const int r0 = ty*4, c0 = tx*4;

    for (int kt = 0; kt < 17; kt++) {
        const int k0g = kt * 64;
        // skip fully-masked K tile (uniform decision across CTA)
        if (q_uni && k0g >= 64) {
            int khi = min(k0g + 63, N_ - 1);
            int kbl = (k0g - 1) >> 8, kbh = (khi - 1) >> 8;
            if (kbl == kbh && kbl == qblk) continue;
        }
        __syncthreads();
        for (int idx = tid; idx < 64*64; idx += 256) {
            int r = idx >> 6, d = idx & 63;
            int kj = k0g + r;
            Ks[r*65 + d] = (kj < N_) ? Kg[(long)kj*64 + d] : 0.f;
            Vs[r*65 + d] = (kj < N_) ? Vg[(long)kj*64 + d] : 0.f;
        }
        __syncthreads();

        float sv[4][4] = {};
        #pragma unroll 8
        for (int kk = 0; kk < 64; kk++) {
            float a[4], b2[4];
            #pragma unroll
            for (int i = 0; i < 4; i++) a[i]  = Qs[(r0+i)*65 + kk];
            #pragma unroll
            for (int j = 0; j < 4; j++) b2[j] = Ks[(c0+j)*65 + kk];
            #pragma unroll
            for (int i = 0; i < 4; i++)
                #pragma unroll
                for (int j = 0; j < 4; j++)
                    sv[i][j] = fmaf(a[i], b2[j], sv[i][j]);
        }

        #pragma unroll
        for (int i = 0; i < 4; i++) {
            int qi = q0g + r0 + i;
            int qb = (qi >= 1) ? ((qi - 1) >> 8) : -1;
            #pragma unroll
            for (int j = 0; j < 4; j++) {
                int kj = k0g + c0 + j;
                float s = sv[i][j] * SCALEF;
                bool bad = (kj >= N_) ||
                           (qb >= 0 && kj >= 1 && (((kj - 1) >> 8) == qb));
                sv[i][j] = bad ? -INFINITY : s;
            }
        }

        #pragma unroll
        for (int i = 0; i < 4; i++) {
            float t = fmaxf(fmaxf(sv[i][0], sv[i][1]), fmaxf(sv[i][2], sv[i][3]));
            #pragma unroll
            for (int o = 8; o >= 1; o >>= 1)
                t = fmaxf(t, __shfl_xor_sync(0xffffffffu, t, o));
            float mnew = fmaxf(m_i[i], t);
            float corr = __expf(m_i[i] - mnew);
            m_i[i] = mnew;

            float p[4], rs = 0.f;
            #pragma unroll
            for (int j = 0; j < 4; j++) {
                p[j] = __expf(sv[i][j] - mnew);
                rs += p[j];
                Ps[(r0+i)*65 + c0 + j] = p[j];
            }
            #pragma unroll
            for (int o = 8; o >= 1; o >>= 1)
                rs += __shfl_xor_sync(0xffffffffu, rs, o);
            l_i[i] = l_i[i] * corr + rs;
            #pragma unroll
            for (int j = 0; j < 4; j++) acc[i][j] *= corr;
        }
        __syncthreads();

        #pragma unroll 8
        for (int jj = 0; jj < 64; jj++) {
            float p[4], v2[4];
            #pragma unroll
            for (int i = 0; i < 4; i++) p[i]  = Ps[(r0+i)*65 + jj];
            #pragma unroll
            for (int j = 0; j < 4; j++) v2[j] = Vs[jj*65 + c0 + j];
            #pragma unroll
            for (int i = 0; i < 4; i++)
                #pragma unroll
                for (int j = 0; j < 4; j++)
                    acc[i][j] = fmaf(p[i], v2[j], acc[i][j]);
        }
    }

    const int b = bh / H_, h = bh % H_;
    #pragma unroll
    for (int i = 0; i < 4; i++) {
        int qi = q0g + r0 + i;
        if (qi < N_) {
            float inv = 1.f / l_i[i];
            long base = ((long)b * N_ + qi) * C_ + h * 64 + c0;
            #pragma unroll
            for (int j = 0; j < 4; j++)
                g_ctx[base + j] = acc[i][j] * inv;
        }
    }
}

// ======================================================================
// Kernel 3: output projection, 128x128 tile, 8x8 per thread.
// ======================================================================
__global__ void __launch_bounds__(256, 2)
out_gemm(const float* __restrict__ W, const float* __restrict__ bias,
         float* __restrict__ out) {
    __shared__ float As[16][136];
    __shared__ float Bs[16][136];
    const int tid = threadIdx.x;
    const int ty = tid >> 4, tx = tid & 15;
    const int m0 = blockIdx.y * 128;
    const int n0 = blockIdx.x * 128;

    float acc[8][8] = {};
    for (int kt = 0; kt < C_; kt += 16) {
        #pragma unroll
        for (int t = 0; t < 8; t++) {
            int idx = tid + t * 256;
            int m = idx >> 4, k = idx & 15;
            int gm = m0 + m;
            As[k][m] = (gm < M_TOT) ? g_ctx[(long)gm * C_ + kt + k] : 0.f;
            int gn = n0 + m;
            Bs[k][m] = W[(long)gn * C_ + kt + k];
        }
        __syncthreads();
        #pragma unroll
        for (int kk = 0; kk < 16; kk++) {
            float a[8], b2[8];
            *(float4*)&a[0]  = *(const float4*)&As[kk][ty*8];
            *(float4*)&a[4]  = *(const float4*)&As[kk][ty*8 + 4];
            *(float4*)&b2[0] = *(const float4*)&Bs[kk][tx*8];
            *(float4*)&b2[4] = *(const float4*)&Bs[kk][tx*8 + 4];
            #pragma unroll
            for (int i = 0; i < 8; i++)
                #pragma unroll
                for (int j = 0; j < 8; j++)
                    acc[i][j] = fmaf(a[i], b2[j], acc[i][j]);
        }
        __syncthreads();
    }
    float bv[8];
    *(float4*)&bv[0] = *(const float4*)&bias[n0 + tx*8];
    *(float4*)&bv[4] = *(const float4*)&bias[n0 + tx*8 + 4];
    #pragma unroll
    for (int i = 0; i < 8; i++) {
        int gm = m0 + ty*8 + i;
        if (gm < M_TOT) {
            long base = OFF_OUT + (long)gm * C_ + n0 + tx*8;
            *(float4*)&out[base]     = make_float4(acc[i][0]+bv[0], acc[i][1]+bv[1],
                                                   acc[i][2]+bv[2], acc[i][3]+bv[3]);
            *(float4*)&out[base + 4] = make_float4(acc[i][4]+bv[4], acc[i][5]+bv[5],
                                                   acc[i][6]+bv[6], acc[i][7]+bv[7]);
        }
    }
}

// ======================================================================
// Kernel 4a: per-head cls softmax row (fp64). One CTA per (b,h), 1024 thr,
// thread-per-key-row dot with 4 independent accumulator chains.
// ======================================================================
__global__ void __launch_bounds__(1024)
cls_head_kernel() {
    __shared__ double q0s[64];
    __shared__ double s[N_];
    __shared__ double red[32];
    const int bh = blockIdx.x;
    const int tid = threadIdx.x;
    const int wid = tid >> 5, lane = tid & 31;

    const float* Qg = g_q + (long)bh * N_ * 64;
    const float* Kg = g_k + (long)bh * N_ * 64;

    if (tid < 64) q0s[tid] = (double)Qg[tid];
    __syncthreads();

    for (int j = tid; j < N_; j += 1024) {
        const float* kr = Kg + (long)j * 64;
        double a0 = 0, a1 = 0, a2 = 0, a3 = 0;
        #pragma unroll
        for (int d = 0; d < 64; d += 4) {
            float4 kv = *(const float4*)&kr[d];
            a0 += q0s[d]     * (double)kv.x;
            a1 += q0s[d + 1] * (double)kv.y;
            a2 += q0s[d + 2] * (double)kv.z;
            a3 += q0s[d + 3] * (double)kv.w;
        }
        s[j] = ((a0 + a1) + (a2 + a3)) * 0.125;
    }
    __syncthreads();

    // block max
    double lm = -1e300;
    for (int j = tid; j < N_; j += 1024) lm = fmax(lm, s[j]);
    #pragma unroll
    for (int o = 16; o >= 1; o >>= 1)
        lm = fmax(lm, __shfl_xor_sync(0xffffffffu, lm, o));
    if (lane == 0) red[wid] = lm;
    __syncthreads();
    if (wid == 0) {
        double t = red[lane];
        #pragma unroll
        for (int o = 16; o >= 1; o >>= 1)
            t = fmax(t, __shfl_xor_sync(0xffffffffu, t, o));
        if (lane == 0) red[0] = t;
    }
    __syncthreads();
    const double m = red[0];
    __syncthreads();

    // exp + block sum (deterministic tree)
    double ls = 0.0;
    for (int j = tid; j < N_; j += 1024) {
        double e = exp(s[j] - m);
        s[j] = e;
        ls += e;
    }
    #pragma unroll
    for (int o = 16; o >= 1; o >>= 1)
        ls += __shfl_xor_sync(0xffffffffu, ls, o);
    if (lane == 0) red[wid] = ls;
    __syncthreads();
    if (wid == 0) {
        double t = red[lane];
        #pragma unroll
        for (int o = 16; o >= 1; o >>= 1)
            t += __shfl_xor_sync(0xffffffffu, t, o);
        if (lane == 0) red[0] = t;
    }
    __syncthreads();
    const double inv = 1.0 / red[0];

    for (int j = tid; j < N_ - 1; j += 1024)
        g_cls_ph[bh][j] = s[j + 1] * inv;
}

// ======================================================================
// Kernel 4b: head-mean reduce (fp64, h-ascending). One CTA per batch.
// ======================================================================
__global__ void cls_reduce_kernel(float* __restrict__ out) {
    const int b = blockIdx.x, tid = threadIdx.x;
    for (int j = tid; j < N_ - 1; j += 256) {
        double a = 0.0;
        #pragma unroll
        for (int h = 0; h < H_; h++)
            a += g_cls_ph[b * H_ + h][j] * (1.0 / 12.0);
        g_clsd[b * (N_ - 1) + j] = a;
        out[OFF_CLS + (long)b * (N_ - 1) + j] = (float)a;
    }
}

// ======================================================================
// Kernel 5: dual bitonic top-k (103 of 1024) on fp64 keys, jax tie-break.
// ======================================================================
__global__ void sort_kernel(float* __restrict__ out) {
    __shared__ double v[1024];
    __shared__ int ix[1024];
    const int b = blockIdx.x, tid = threadIdx.x;

    for (int pass = 0; pass < 2; pass++) {
        __syncthreads();
        for (int i = tid; i < 1024; i += 512) {
            v[i] = g_clsd[b * 1024 + i];
            ix[i] = i;
        }
        __syncthreads();
        const bool desc = (pass == 0);
        for (int k = 2; k <= 1024; k <<= 1) {
            for (int j = k >> 1; j > 0; j >>= 1) {
                for (int i = tid; i < 1024; i += 512) {
                    int p = i ^ j;
                    if (p > i) {
                        double va = v[i], vb = v[p];
                        int ia = ix[i], ib = ix[p];
                        bool ab = desc ? (va > vb || (va == vb && ia < ib))
                                       : (va < vb || (va == vb && ia < ib));
                        bool up = ((i & k) == 0);
                        if (up ? !ab : ab) {
                            v[i] = vb; v[p] = va;
                            ix[i] = ib; ix[p] = ia;
                        }
                    }
                }
                __syncthreads();
            }
        }
        const long offIdx = desc ? OFF_ENH_IDX : OFF_FUSE_IDX;
        const long offBrd = desc ? OFF_ENH_INDEX : OFF_FUSE_INDEX;
        for (int t = tid; t < TOPT; t += 512)
            out[offIdx + (long)b * TOPT + t] = (float)ix[t];
        for (int e = tid; e < TOPT * C_; e += 512) {
            int t = e / C_;
            out[offBrd + ((long)b * TOPT + t) * C_ + (e % C_)] = (float)ix[t];
        }
    }
}

// ======================================================================
// Launch
// ======================================================================
extern "C" void kernel_launch(void* const* d_in, const int* in_sizes, int n_in,
                              void* d_out, int out_size) {
    const float* x     = (const float*)d_in[0];
    const float* w_qkv = (const float*)d_in[1];
    const float* w_out = (const float*)d_in[2];
    const float* b_out = (const float*)d_in[3];
    float* out = (float*)d_out;

    const int ATTN_SMEM = 4 * 64 * 65 * (int)sizeof(float);   // 66560 B
    cudaFuncSetAttribute(attn_kernel, cudaFuncAttributeMaxDynamicSharedMemorySize,
                         ATTN_SMEM);

    qkv_gemm<<<dim3(3 * C_ / 128, (M_TOT + 127) / 128), 256>>>(x, w_qkv);
    attn_kernel<<<dim3(17, B_ * H_), 256, ATTN_SMEM>>>();
    out_gemm<<<dim3(C_ / 128, (M_TOT + 127) / 128), 256>>>(w_out, b_out, out);
    cls_head_kernel<<<B_ * H_, 1024>>>();
    cls_reduce_kernel<<<B_, 256>>>(out);
    sort_kernel<<<B_, 512>>>(out);
}